// round 7
// baseline (speedup 1.0000x reference)
#include <cuda_runtime.h>

// ---------------------------------------------------------------------------
// ST_Block: 66-step spatio-temporal orthogonal basis recursion + fused MLP/BN.
//
// Per step r the producing GEMM kernel also emits 6 full-slab dot products
// (deterministic tree reduction into g_part ping-pong, 8 tiles). The *next*
// kernel derives the Gram-Schmidt coefficients + analytic residual norm from
// those scalars and performs the normalization + theta-accumulation as a
// region-local prologue (fused update). Only the very last step needs a
// standalone update. 69 graph nodes total, no atomics.
//
// R7 change vs R6: temporal kernel moved to 64-row tiles + 4x4 thread tile
// (16 FFMA per LDS-wavefront-pair instead of 8) -> FFMA-bound, not LSU-bound.
// Both GEMMs now emit 8 partial tiles (g_part simplified).
// ---------------------------------------------------------------------------

#define BB   4
#define CC   16
#define CH   64              // B*C chains
#define NN   512
#define TT   64
#define SLAB (NN*TT)         // 32768 floats per chain slab
#define CSZ  (CH*SLAB)       // floats per full slab
#define NSLAB 7
#define ACCS  6              // slab index reserved for x_st accumulator
#define RTOT  66

__device__ __align__(16) float g_slab[NSLAB * CSZ];   // ~58.7 MB scratch
__device__ float g_part[2][CH][8][6];                 // ping-pong dot partials
__device__ float g_theta[BB][RTOT];

__device__ __forceinline__ float warp_sum(float v) {
    v += __shfl_down_sync(0xffffffffu, v, 16);
    v += __shfl_down_sync(0xffffffffu, v, 8);
    v += __shfl_down_sync(0xffffffffu, v, 4);
    v += __shfl_down_sync(0xffffffffu, v, 2);
    v += __shfl_down_sync(0xffffffffu, v, 1);
    return v;
}

// Derive d1, d2, 1/norm, theta from the 6 summed dots.
//   d1 = <V,L>;  d2 = <V,S> - d1*<L,S>
//   ||rst2||^2 = p3 - 2 d1 p1 - 2 d2 p2 + d1^2 p5 + d2^2 p6 + 2 d1 d2 p4
__device__ __forceinline__ void derive_scalars(int readPP, int chain, int rUpd,
                                               float* sc) {
    float p[6];
    #pragma unroll
    for (int c = 0; c < 6; c++) {
        float t = 0.f;
        #pragma unroll
        for (int tl = 0; tl < 8; tl++) t += g_part[readPP][chain][tl][c];
        p[c] = t;
    }
    float d1 = p[0];
    float d2 = p[1] - d1 * p[3];
    float n2 = p[2] - 2.f * d1 * p[0] - 2.f * d2 * p[1]
             + d1 * d1 * p[4] + d2 * d2 * p[5] + 2.f * d1 * d2 * p[3];
    sc[0] = d1;
    sc[1] = d2;
    sc[2] = 1.f / fmaxf(sqrtf(fmaxf(n2, 0.f)), 1e-8f);
    sc[3] = g_theta[chain >> 4][rUpd];
}

// ---------------------------------------------------------------------------
// theta: tiny MLP on STE. theta[b][q*11+p] = relu(h2[b,p,q])
// ---------------------------------------------------------------------------
__global__ void k_theta(const float* __restrict__ STE, const float* __restrict__ w1,
                        const float* __restrict__ b1, const float* __restrict__ w2,
                        const float* __restrict__ b2) {
    int idx = threadIdx.x;
    if (idx >= BB * RTOT) return;
    int b = idx / RTOT, rr = idx % RTOT;
    int q = rr / 11, p = rr % 11;
    float acc = b2[p];
    #pragma unroll
    for (int s = 0; s < 10; s++) {
        float h1 = b1[q];
        #pragma unroll
        for (int t = 0; t < 5; t++)
            h1 += w1[q * 5 + t] * STE[b * 50 + t * 10 + s];
        acc += w2[p * 10 + s] * h1;
    }
    g_theta[b][rr] = fmaxf(acc, 0.f);
}

// ---------------------------------------------------------------------------
// init: m00 = x / max(||x||_F, eps) into slab 0; acc = theta_0 * m00
// ---------------------------------------------------------------------------
__global__ void __launch_bounds__(256) k_init(const float* __restrict__ x) {
    int chain = blockIdx.x;
    const float* xp = x + chain * SLAB;
    float* m = g_slab + 0 * CSZ + chain * SLAB;
    float* a = g_slab + ACCS * CSZ + chain * SLAB;
    int tid = threadIdx.x;

    float s = 0.f;
    #pragma unroll
    for (int i = 0; i < 32; i++) {
        float4 v = *(const float4*)(xp + (i * 256 + tid) * 4);
        s += v.x * v.x + v.y * v.y + v.z * v.z + v.w * v.w;
    }
    __shared__ float red[8];
    __shared__ float sinv;
    float w = warp_sum(s);
    if ((tid & 31) == 0) red[tid >> 5] = w;
    __syncthreads();
    if (tid == 0) {
        float t = 0.f;
        #pragma unroll
        for (int k = 0; k < 8; k++) t += red[k];
        sinv = 1.f / fmaxf(sqrtf(t), 1e-8f);
    }
    __syncthreads();
    float inv = sinv;
    float th = g_theta[chain >> 4][0];
    #pragma unroll
    for (int i = 0; i < 32; i++) {
        int o = (i * 256 + tid) * 4;
        float4 v = *(const float4*)(xp + o);
        float4 mm, aa;
        mm.x = v.x * inv; mm.y = v.y * inv; mm.z = v.z * inv; mm.w = v.w * inv;
        aa.x = th * mm.x; aa.y = th * mm.y; aa.z = th * mm.z; aa.w = th * mm.w;
        *(float4*)(m + o) = mm;
        *(float4*)(a + o) = aa;
    }
}

// ---------------------------------------------------------------------------
// fused temporal kernel: [optional regional update of updV -> m (into smem
// and gmem) + x_st accumulation] then V_out[n][u] = sum_t m[n][t] * Lt[t][u]
// with fused 6-dot partials. Block = (chain, 64-row tile) -> grid (64,8).
// Thread tile 4x4 -> 16 FFMA per k-step per thread; ~35 KB smem.
// Invariant: when updV >= 0, updV == inIdx (the GEMM input is the slab
// being updated), so the prologue feeds sX directly.
// ---------------------------------------------------------------------------
__global__ void __launch_bounds__(256) k_fusedT(
    const float* __restrict__ Lt,
    int updV, int updL, int updS, int rUpd,
    int inIdx, int secIdx, int outIdx,
    int readPP, int writePP)
{
    __shared__ float sL[64][68];      // full Lt
    __shared__ float sX[64][68];      // m tile, [n_local][t]
    __shared__ float scal[4];
    __shared__ float red[8][6];
    int chain = blockIdx.x, rt = blockIdx.y, tid = threadIdx.x;
    int base = chain * SLAB + rt * 64 * TT;

    // Lt load (independent of the prologue; overlaps it)
    #pragma unroll
    for (int it = 0; it < 4; it++) {
        int li = it * 256 + tid;                 // 0..1023
        int r = li >> 4, c4 = (li & 15) << 2;
        *(float4*)&sL[r][c4] = *(const float4*)(Lt + r * TT + c4);
    }

    if (updV >= 0) {
        if (tid == 0) derive_scalars(readPP, chain, rUpd, scal);
        __syncthreads();
        float d1 = scal[0], d2 = scal[1], inv = scal[2], th = scal[3];
        float* V = g_slab + updV * CSZ + base;
        const float* L = g_slab + updL * CSZ + base;
        const float* S = (updS >= 0) ? (g_slab + updS * CSZ + base) : nullptr;
        float* A = g_slab + ACCS * CSZ + base;
        #pragma unroll
        for (int it = 0; it < 4; it++) {
            int idx = it * 256 + tid;            // 0..1023
            int n = idx >> 4, t4 = (idx & 15) << 2;
            int o = n * TT + t4;
            float4 v = *(float4*)(V + o);
            float4 l = *(const float4*)(L + o);
            float4 s4 = S ? *(const float4*)(S + o) : make_float4(0.f, 0.f, 0.f, 0.f);
            float4 m;
            m.x = (v.x - d1 * l.x - d2 * s4.x) * inv;
            m.y = (v.y - d1 * l.y - d2 * s4.y) * inv;
            m.z = (v.z - d1 * l.z - d2 * s4.z) * inv;
            m.w = (v.w - d1 * l.w - d2 * s4.w) * inv;
            *(float4*)(V + o) = m;
            float4 a = *(float4*)(A + o);
            a.x += th * m.x; a.y += th * m.y; a.z += th * m.z; a.w += th * m.w;
            *(float4*)(A + o) = a;
            *(float4*)&sX[n][t4] = m;
        }
    } else {
        const float* X = g_slab + inIdx * CSZ + base;
        #pragma unroll
        for (int it = 0; it < 4; it++) {
            int idx = it * 256 + tid;
            int n = idx >> 4, t4 = (idx & 15) << 2;
            *(float4*)&sX[n][t4] = *(const float4*)(X + n * TT + t4);
        }
    }
    __syncthreads();

    int tx = tid & 15, ty = tid >> 4;
    float acc[4][4] = {};
    #pragma unroll 8
    for (int k = 0; k < 64; k++) {
        float b4[4];
        *(float4*)b4 = *(float4*)&sL[k][tx << 2];
        float a[4];
        #pragma unroll
        for (int i = 0; i < 4; i++) a[i] = sX[ty + 16 * i][k];
        #pragma unroll
        for (int i = 0; i < 4; i++)
            #pragma unroll
            for (int j = 0; j < 4; j++) acc[i][j] += a[i] * b4[j];
    }

    float* V = g_slab + outIdx * CSZ + base;
    const float* S2 = (secIdx >= 0) ? (g_slab + secIdx * CSZ + base) : nullptr;
    float p1 = 0, p2 = 0, p3 = 0, p4 = 0, p5 = 0, p6 = 0;
    #pragma unroll
    for (int i = 0; i < 4; i++) {
        int n = ty + 16 * i;
        float4 lv = *(float4*)&sX[n][tx << 2];
        float4 sv = S2 ? *(const float4*)(S2 + n * TT + (tx << 2))
                       : make_float4(0.f, 0.f, 0.f, 0.f);
        float4 vv = make_float4(acc[i][0], acc[i][1], acc[i][2], acc[i][3]);
        *(float4*)(V + n * TT + (tx << 2)) = vv;
        p1 += vv.x * lv.x + vv.y * lv.y + vv.z * lv.z + vv.w * lv.w;
        p2 += vv.x * sv.x + vv.y * sv.y + vv.z * sv.z + vv.w * sv.w;
        p3 += vv.x * vv.x + vv.y * vv.y + vv.z * vv.z + vv.w * vv.w;
        p4 += lv.x * sv.x + lv.y * sv.y + lv.z * sv.z + lv.w * sv.w;
        p5 += lv.x * lv.x + lv.y * lv.y + lv.z * lv.z + lv.w * lv.w;
        p6 += sv.x * sv.x + sv.y * sv.y + sv.z * sv.z + sv.w * sv.w;
    }
    float r6[6] = {p1, p2, p3, p4, p5, p6};
    #pragma unroll
    for (int s = 0; s < 6; s++) {
        float w = warp_sum(r6[s]);
        if ((tid & 31) == 0) red[tid >> 5][s] = w;
    }
    __syncthreads();
    if (tid < 6) {
        float t = 0.f;
        #pragma unroll
        for (int w = 0; w < 8; w++) t += red[w][tid];
        g_part[writePP][chain][rt][tid] = t;
    }
}

// ---------------------------------------------------------------------------
// fused spatial kernel: [optional regional update of updV slab (independent
// of the GEMM operands)] then V[n][t] = sum_m Ls[n][m] * X[m][t], K=512 in
// 8 chunks of 64, with fused 6-dot partials.
// Block = (chain, 64-row tile) -> grid (64,8). Thread tile 4x4.
// ---------------------------------------------------------------------------
__global__ void __launch_bounds__(256) k_spatial(
    const float* __restrict__ Ls,
    int updV, int updL, int updS, int rUpd,
    int inIdx, int secIdx, int outIdx,
    int readPP, int writePP)
{
    __shared__ float sA[64][68];      // Ls rows chunk, [n_local][k_local]
    __shared__ float sB[64][68];      // X chunk, [k_local][t]
    __shared__ float scal[4];
    __shared__ float red[8][6];
    int chain = blockIdx.x, nt = blockIdx.y, tid = threadIdx.x;
    int base = chain * SLAB + nt * 64 * TT;

    if (updV >= 0) {
        if (tid == 0) derive_scalars(readPP, chain, rUpd, scal);
        __syncthreads();
        float d1 = scal[0], d2 = scal[1], inv = scal[2], th = scal[3];
        float* V = g_slab + updV * CSZ + base;
        const float* L = g_slab + updL * CSZ + base;
        const float* S = (updS >= 0) ? (g_slab + updS * CSZ + base) : nullptr;
        float* A = g_slab + ACCS * CSZ + base;
        #pragma unroll
        for (int it = 0; it < 4; it++) {
            int idx = it * 256 + tid;            // 0..1023
            int n = idx >> 4, t4 = (idx & 15) << 2;
            int o = n * TT + t4;
            float4 v = *(float4*)(V + o);
            float4 l = *(const float4*)(L + o);
            float4 s4 = S ? *(const float4*)(S + o) : make_float4(0.f, 0.f, 0.f, 0.f);
            float4 m;
            m.x = (v.x - d1 * l.x - d2 * s4.x) * inv;
            m.y = (v.y - d1 * l.y - d2 * s4.y) * inv;
            m.z = (v.z - d1 * l.z - d2 * s4.z) * inv;
            m.w = (v.w - d1 * l.w - d2 * s4.w) * inv;
            *(float4*)(V + o) = m;
            float4 a = *(float4*)(A + o);
            a.x += th * m.x; a.y += th * m.y; a.z += th * m.z; a.w += th * m.w;
            *(float4*)(A + o) = a;
        }
    }

    const float* Xc = g_slab + inIdx * CSZ + chain * SLAB;   // full slab (read only)
    int tx = tid & 15, ty = tid >> 4;
    float acc[4][4] = {};
    for (int kc = 0; kc < 8; kc++) {
        __syncthreads();
        #pragma unroll
        for (int it = 0; it < 4; it++) {
            int li = it * 256 + tid;
            int r = li >> 4, c4 = (li & 15) << 2;
            *(float4*)&sA[r][c4] =
                *(const float4*)(Ls + (nt * 64 + r) * NN + kc * 64 + c4);
            *(float4*)&sB[r][c4] = *(const float4*)(Xc + (kc * 64 + r) * TT + c4);
        }
        __syncthreads();
        #pragma unroll 8
        for (int k = 0; k < 64; k++) {
            float b4[4];
            *(float4*)b4 = *(float4*)&sB[k][tx << 2];
            float a[4];
            #pragma unroll
            for (int i = 0; i < 4; i++) a[i] = sA[ty + 16 * i][k];
            #pragma unroll
            for (int i = 0; i < 4; i++)
                #pragma unroll
                for (int j = 0; j < 4; j++) acc[i][j] += a[i] * b4[j];
        }
    }

    const float* Lrows = Xc + nt * 64 * TT;   // last_s values at output rows
    const float* S2 = (secIdx >= 0) ? (g_slab + secIdx * CSZ + base) : nullptr;
    float* V = g_slab + outIdx * CSZ + base;
    float p1 = 0, p2 = 0, p3 = 0, p4 = 0, p5 = 0, p6 = 0;
    #pragma unroll
    for (int i = 0; i < 4; i++) {
        int n = ty + 16 * i;
        float4 lv = *(const float4*)(Lrows + n * TT + (tx << 2));
        float4 sv = S2 ? *(const float4*)(S2 + n * TT + (tx << 2))
                       : make_float4(0.f, 0.f, 0.f, 0.f);
        float4 vv = make_float4(acc[i][0], acc[i][1], acc[i][2], acc[i][3]);
        *(float4*)(V + n * TT + (tx << 2)) = vv;
        p1 += vv.x * lv.x + vv.y * lv.y + vv.z * lv.z + vv.w * lv.w;
        p2 += vv.x * sv.x + vv.y * sv.y + vv.z * sv.z + vv.w * sv.w;
        p3 += vv.x * vv.x + vv.y * vv.y + vv.z * vv.z + vv.w * vv.w;
        p4 += lv.x * sv.x + lv.y * sv.y + lv.z * sv.z + lv.w * sv.w;
        p5 += lv.x * lv.x + lv.y * lv.y + lv.z * lv.z + lv.w * lv.w;
        p6 += sv.x * sv.x + sv.y * sv.y + sv.z * sv.z + sv.w * sv.w;
    }
    float r6[6] = {p1, p2, p3, p4, p5, p6};
    #pragma unroll
    for (int s = 0; s < 6; s++) {
        float w = warp_sum(r6[s]);
        if ((tid & 31) == 0) red[tid >> 5][s] = w;
    }
    __syncthreads();
    if (tid < 6) {
        float t = 0.f;
        #pragma unroll
        for (int w = 0; w < 8; w++) t += red[w][tid];
        g_part[writePP][chain][nt][tid] = t;
    }
}

// ---------------------------------------------------------------------------
// standalone update (used once, for r=65): A += theta * m   (m not persisted)
// ---------------------------------------------------------------------------
__global__ void __launch_bounds__(256) k_update(int vIdx, int lIdx, int sIdx,
                                                int rUpd, int readPP) {
    int chain = blockIdx.x, seg = blockIdx.y;
    __shared__ float scal[4];
    int tid = threadIdx.x;
    if (tid == 0) derive_scalars(readPP, chain, rUpd, scal);
    __syncthreads();
    float d1 = scal[0], d2 = scal[1], inv = scal[2], th = scal[3];

    int base = chain * SLAB + seg * 2048;
    const float* V = g_slab + vIdx * CSZ + base;
    const float* L = g_slab + lIdx * CSZ + base;
    const float* S = (sIdx >= 0) ? (g_slab + sIdx * CSZ + base) : nullptr;
    float* A = g_slab + ACCS * CSZ + base;
    #pragma unroll
    for (int it = 0; it < 2; it++) {
        int o = (it * 256 + tid) * 4;
        float4 v = *(const float4*)(V + o);
        float4 l = *(const float4*)(L + o);
        float4 s4 = S ? *(const float4*)(S + o) : make_float4(0.f, 0.f, 0.f, 0.f);
        float4 a = *(float4*)(A + o);
        a.x += th * (v.x - d1 * l.x - d2 * s4.x) * inv;
        a.y += th * (v.y - d1 * l.y - d2 * s4.y) * inv;
        a.z += th * (v.z - d1 * l.z - d2 * s4.z) * inv;
        a.w += th * (v.w - d1 * l.w - d2 * s4.w) * inv;
        *(float4*)(A + o) = a;
    }
}

// ---------------------------------------------------------------------------
// final: out[b,o,n,t] = BN(W_mlp @ cat(x, x_st) + b)   with BN folded into W,b
// ---------------------------------------------------------------------------
__global__ void __launch_bounds__(256) k_final(const float* __restrict__ x,
                                               const float* __restrict__ wm,
                                               const float* __restrict__ bm,
                                               const float* __restrict__ gam,
                                               const float* __restrict__ bet,
                                               const float* __restrict__ mea,
                                               const float* __restrict__ var,
                                               float* __restrict__ out) {
    int b = blockIdx.x;
    int ng = blockIdx.y;                 // group of 4 n values
    __shared__ float sV[4][32][65];
    __shared__ float sW[64][32];
    __shared__ float sb2[64];
    int tid = threadIdx.x;

    for (int i = tid; i < 2048; i += 256) {
        int o = i >> 5, c = i & 31;
        float inv = gam[o] * rsqrtf(var[o] + 1e-5f);
        sW[o][c] = wm[o * 32 + c] * inv;
    }
    if (tid < 64) {
        float inv = gam[tid] * rsqrtf(var[tid] + 1e-5f);
        sb2[tid] = bm[tid] * inv + bet[tid] - mea[tid] * inv;
    }
    for (int i = tid; i < 8192; i += 256) {
        int t = i & 63, c = (i >> 6) & 31, nn = i >> 11;
        int n = ng * 4 + nn;
        float val;
        if (c < 16) val = x[((b * CC + c) * NN + n) * TT + t];
        else        val = g_slab[ACCS * CSZ + (b * CC + (c - 16)) * SLAB + n * TT + t];
        sV[nn][c][t] = val;
    }
    __syncthreads();

    int tg = tid & 63, og = tid >> 6;
    for (int oo = 0; oo < 16; oo++) {
        int o = og * 16 + oo;
        float w[32];
        #pragma unroll
        for (int c = 0; c < 32; c++) w[c] = sW[o][c];
        float bb = sb2[o];
        #pragma unroll
        for (int nn = 0; nn < 4; nn++) {
            float s = bb;
            #pragma unroll
            for (int c = 0; c < 32; c++) s += w[c] * sV[nn][c][tg];
            int n = ng * 4 + nn;
            out[((b * 64 + o) * NN + n) * TT + tg] = s;
        }
    }
}

// ---------------------------------------------------------------------------
// host: 69-node launch sequence (graph-capturable: launches only)
// ---------------------------------------------------------------------------
extern "C" void kernel_launch(void* const* d_in, const int* in_sizes, int n_in,
                              void* d_out, int out_size) {
    const float* x   = (const float*)d_in[0];
    const float* Ls  = (const float*)d_in[1];
    const float* Lt  = (const float*)d_in[2];
    const float* STE = (const float*)d_in[3];
    const float* w1  = (const float*)d_in[4];
    const float* b1  = (const float*)d_in[5];
    const float* w2  = (const float*)d_in[6];
    const float* b2  = (const float*)d_in[7];
    const float* wm  = (const float*)d_in[8];
    const float* bm  = (const float*)d_in[9];
    const float* gam = (const float*)d_in[10];
    const float* bet = (const float*)d_in[11];
    const float* mea = (const float*)d_in[12];
    const float* var = (const float*)d_in[13];
    float* out = (float*)d_out;
    (void)in_sizes; (void)n_in; (void)out_size;

    k_theta<<<1, 288>>>(STE, w1, b1, w2, b2);
    k_init<<<64, 256>>>(x);

    struct Pend { int v, l, s, r, pp; };
    Pend pend{-1, -1, -1, -1, 0};
    int pp = 0;
    int last_s = 0, sec_s = -1, last_t = 0, sec_t = -1;
    int r = 1;
    auto pick = [&]() {
        for (int k = 0; k < 6; k++)
            if (k != last_s && k != sec_s && k != last_t && k != sec_t) return k;
        return -1;
    };
    for (int i = 0; i <= 10; i++) {
        if (i > 0) {
            int f = pick();
            k_spatial<<<dim3(64, 8), 256>>>(Ls, pend.v, pend.l, pend.s, pend.r,
                                            last_s, sec_s, f, pend.pp, pp);
            pend = {f, last_s, sec_s, r, pp}; pp ^= 1;
            sec_s = last_s; last_s = f; last_t = f; sec_t = -1; r++;
        }
        for (int j = 0; j < 5; j++) {
            int f = pick();
            k_fusedT<<<dim3(64, 8), 256>>>(Lt, pend.v, pend.l, pend.s, pend.r,
                                           last_t, sec_t, f, pend.pp, pp);
            pend = {f, last_t, sec_t, r, pp}; pp ^= 1;
            sec_t = last_t; last_t = f; r++;
        }
    }
    k_update<<<dim3(64, 16), 256>>>(pend.v, pend.l, pend.s, pend.r, pend.pp);
    k_final<<<dim3(4, 128), 256>>>(x, wm, bm, gam, bet, mea, var, out);
}

// round 8
// speedup vs baseline: 1.4653x; 1.4653x over previous
#include <cuda_runtime.h>

// ---------------------------------------------------------------------------
// ST_Block: 66-step spatio-temporal orthogonal basis recursion + fused MLP/BN.
//
// R8: single persistent cooperative kernel runs all 65 recursion steps with
// an atomic grid barrier between phases (eliminates 67 launch boundaries).
// Block b owns tiles {b, b+256} (tile = (chain, 64-row group)) for EVERY
// phase, so the deferred Gram-Schmidt update (scalars from the previous
// phase's 6 global dots) stays tile-local. All mutable global traffic uses
// __ldcg/__stcg (L2-coherent; persistent kernels get no per-launch L1 flush).
// The accumulator slab is tile-owner-private -> may use L1. Ls/Lt/x are
// immutable -> L1-cached (Ls rows stay hot across all 10 spatial phases).
// ---------------------------------------------------------------------------

#define BB   4
#define CC   16
#define CH   64              // B*C chains
#define NN   512
#define TT   64
#define SLAB (NN*TT)         // 32768 floats per chain slab
#define CSZ  (CH*SLAB)       // floats per full slab
#define NSLAB 7
#define ACCS  6              // slab index reserved for x_st accumulator
#define RTOT  66
#define NB    256            // persistent grid size (co-residency guaranteed)

__device__ __align__(16) float g_slab[NSLAB * CSZ];   // ~58.7 MB scratch
__device__ float g_part[2][CH][8][6];                 // ping-pong dot partials
__device__ float g_theta[BB][RTOT];
__device__ unsigned g_bar_count;
__device__ volatile unsigned g_bar_gen;

__device__ __forceinline__ float4 ldcg4(const float* p) {
    return __ldcg((const float4*)p);
}
__device__ __forceinline__ void stcg4(float* p, float4 v) {
    __stcg((float4*)p, v);
}

__device__ __forceinline__ float warp_sum(float v) {
    v += __shfl_down_sync(0xffffffffu, v, 16);
    v += __shfl_down_sync(0xffffffffu, v, 8);
    v += __shfl_down_sync(0xffffffffu, v, 4);
    v += __shfl_down_sync(0xffffffffu, v, 2);
    v += __shfl_down_sync(0xffffffffu, v, 1);
    return v;
}

// Grid-wide barrier. Producer writes are made visible by the gpu-scope fence
// after the CTA-level __syncthreads (release pattern); waiters fence after
// observing the generation flip (acquire). All NB blocks are co-resident by
// construction, so the spin cannot deadlock.
__device__ __forceinline__ void grid_sync() {
    __syncthreads();
    if (threadIdx.x == 0) {
        __threadfence();
        unsigned gen = g_bar_gen;
        if (atomicAdd(&g_bar_count, 1u) == NB - 1) {
            g_bar_count = 0;
            __threadfence();
            g_bar_gen = gen + 1;
        } else {
            while (g_bar_gen == gen) __nanosleep(64);
        }
        __threadfence();
    }
    __syncthreads();
}

// Derive d1, d2, 1/norm, theta from the 6 summed dots (L2-coherent reads).
//   d1 = <V,L>;  d2 = <V,S> - d1*<L,S>
//   ||rst2||^2 = p3 - 2 d1 p1 - 2 d2 p2 + d1^2 p5 + d2^2 p6 + 2 d1 d2 p4
__device__ __forceinline__ void derive_scalars(int readPP, int chain, int rUpd,
                                               float* sc) {
    float p0 = 0, p1 = 0, p2 = 0, p3 = 0, p4 = 0, p5 = 0;
    #pragma unroll
    for (int tl = 0; tl < 8; tl++) {
        const float* q = &g_part[readPP][chain][tl][0];
        p0 += __ldcg(q + 0); p1 += __ldcg(q + 1); p2 += __ldcg(q + 2);
        p3 += __ldcg(q + 3); p4 += __ldcg(q + 4); p5 += __ldcg(q + 5);
    }
    float d1 = p0;
    float d2 = p1 - d1 * p3;
    float n2 = p2 - 2.f * d1 * p0 - 2.f * d2 * p1
             + d1 * d1 * p4 + d2 * d2 * p5 + 2.f * d1 * d2 * p3;
    sc[0] = d1;
    sc[1] = d2;
    sc[2] = 1.f / fmaxf(sqrtf(fmaxf(n2, 0.f)), 1e-8f);
    sc[3] = g_theta[chain >> 4][rUpd];
}

// Tile-local pending update: V <- m = (V - d1 L - d2 S)/norm ; A += theta*m.
// Optionally also deposits m into smem (temporal phases feed the GEMM).
__device__ __forceinline__ void update_tile(int base, int pV, int pL, int pS,
                                            const float* sc, float (*s1)[68],
                                            bool toSmem, int tid) {
    float d1 = sc[0], d2 = sc[1], inv = sc[2], th = sc[3];
    float*       V  = g_slab + pV * CSZ + base;
    const float* Lp = g_slab + pL * CSZ + base;
    const float* Sp = (pS >= 0) ? (g_slab + pS * CSZ + base) : nullptr;
    float*       A  = g_slab + ACCS * CSZ + base;
    #pragma unroll
    for (int it = 0; it < 4; it++) {
        int idx = it * 256 + tid;            // 0..1023 float4s over the tile
        int o = idx * 4;
        float4 v = ldcg4(V + o);
        float4 l = ldcg4(Lp + o);
        float4 s4 = Sp ? ldcg4(Sp + o) : make_float4(0.f, 0.f, 0.f, 0.f);
        float4 m;
        m.x = (v.x - d1 * l.x - d2 * s4.x) * inv;
        m.y = (v.y - d1 * l.y - d2 * s4.y) * inv;
        m.z = (v.z - d1 * l.z - d2 * s4.z) * inv;
        m.w = (v.w - d1 * l.w - d2 * s4.w) * inv;
        stcg4(V + o, m);
        float4 a = *(float4*)(A + o);        // A is tile-owner-private: L1 OK
        a.x += th * m.x; a.y += th * m.y; a.z += th * m.z; a.w += th * m.w;
        *(float4*)(A + o) = a;
        if (toSmem) {
            int n = idx >> 4, t4 = (idx & 15) << 2;
            *(float4*)&s1[n][t4] = m;
        }
    }
}

// ---------------------------------------------------------------------------
// theta: tiny MLP on STE. theta[b][q*11+p] = relu(h2[b,p,q])
// ---------------------------------------------------------------------------
__global__ void k_theta(const float* __restrict__ STE, const float* __restrict__ w1,
                        const float* __restrict__ b1, const float* __restrict__ w2,
                        const float* __restrict__ b2) {
    int idx = threadIdx.x;
    if (idx >= BB * RTOT) return;
    int b = idx / RTOT, rr = idx % RTOT;
    int q = rr / 11, p = rr % 11;
    float acc = b2[p];
    #pragma unroll
    for (int s = 0; s < 10; s++) {
        float h1 = b1[q];
        #pragma unroll
        for (int t = 0; t < 5; t++)
            h1 += w1[q * 5 + t] * STE[b * 50 + t * 10 + s];
        acc += w2[p * 10 + s] * h1;
    }
    g_theta[b][rr] = fmaxf(acc, 0.f);
}

// ---------------------------------------------------------------------------
// init: m00 = x / max(||x||_F, eps) into slab 0; acc = theta_0 * m00
// ---------------------------------------------------------------------------
__global__ void __launch_bounds__(256) k_init(const float* __restrict__ x) {
    int chain = blockIdx.x;
    const float* xp = x + chain * SLAB;
    float* m = g_slab + 0 * CSZ + chain * SLAB;
    float* a = g_slab + ACCS * CSZ + chain * SLAB;
    int tid = threadIdx.x;

    float s = 0.f;
    #pragma unroll
    for (int i = 0; i < 32; i++) {
        float4 v = *(const float4*)(xp + (i * 256 + tid) * 4);
        s += v.x * v.x + v.y * v.y + v.z * v.z + v.w * v.w;
    }
    __shared__ float red[8];
    __shared__ float sinv;
    float w = warp_sum(s);
    if ((tid & 31) == 0) red[tid >> 5] = w;
    __syncthreads();
    if (tid == 0) {
        float t = 0.f;
        #pragma unroll
        for (int k = 0; k < 8; k++) t += red[k];
        sinv = 1.f / fmaxf(sqrtf(t), 1e-8f);
    }
    __syncthreads();
    float inv = sinv;
    float th = g_theta[chain >> 4][0];
    #pragma unroll
    for (int i = 0; i < 32; i++) {
        int o = (i * 256 + tid) * 4;
        float4 v = *(const float4*)(xp + o);
        float4 mm, aa;
        mm.x = v.x * inv; mm.y = v.y * inv; mm.z = v.z * inv; mm.w = v.w * inv;
        aa.x = th * mm.x; aa.y = th * mm.y; aa.z = th * mm.z; aa.w = th * mm.w;
        *(float4*)(m + o) = mm;
        *(float4*)(a + o) = aa;
    }
}

// ---------------------------------------------------------------------------
// persistent kernel: all 65 steps + final pending update.
// Tile tt = (chain = tt>>3, rowTile = tt&7); block b owns tiles {b, b+256}.
// ---------------------------------------------------------------------------
__global__ void __launch_bounds__(256, 2) k_persist(
    const float* __restrict__ Ls, const float* __restrict__ Lt)
{
    __shared__ float s0[64][68];
    __shared__ float s1[64][68];
    __shared__ float scal[4];
    __shared__ float red[8][6];
    const int tid = threadIdx.x, bid = blockIdx.x;
    const int tx = tid & 15, ty = tid >> 4;

    int last_s = 0, sec_s = -1, last_t = 0, sec_t = -1;
    int pV = -1, pL = -1, pS = -1, pR = 0, pPP = 0;
    int pp = 0, r = 1;

    for (int i = 0; i <= 10; i++) {
        if (i > 0) {
            int f = -1;
            #pragma unroll
            for (int k = 5; k >= 0; k--)
                if (k != last_s && k != sec_s && k != last_t && k != sec_t) f = k;
            // ---------------- SPATIAL PHASE (step r) ----------------
            #pragma unroll 1
            for (int tt = bid; tt < 512; tt += NB) {
                int chain = tt >> 3, rt = tt & 7;
                int base = chain * SLAB + rt * 64 * TT;
                if (pV >= 0) {
                    if (tid == 0) derive_scalars(pPP, chain, pR, scal);
                    __syncthreads();
                    update_tile(base, pV, pL, pS, scal, s1, false, tid);
                }
                const float* Xc = g_slab + last_s * CSZ + chain * SLAB;
                float acc[4][4] = {};
                for (int kc = 0; kc < 8; kc++) {
                    __syncthreads();
                    #pragma unroll
                    for (int it = 0; it < 4; it++) {
                        int li = it * 256 + tid;
                        int rr = li >> 4, c4 = (li & 15) << 2;
                        *(float4*)&s0[rr][c4] =
                            *(const float4*)(Ls + (rt * 64 + rr) * NN + kc * 64 + c4);
                        *(float4*)&s1[rr][c4] = ldcg4(Xc + (kc * 64 + rr) * TT + c4);
                    }
                    __syncthreads();
                    #pragma unroll 8
                    for (int k = 0; k < 64; k++) {
                        float b4[4];
                        *(float4*)b4 = *(float4*)&s1[k][tx << 2];
                        float a4[4];
                        #pragma unroll
                        for (int ii = 0; ii < 4; ii++) a4[ii] = s0[ty + 16 * ii][k];
                        #pragma unroll
                        for (int ii = 0; ii < 4; ii++)
                            #pragma unroll
                            for (int j = 0; j < 4; j++) acc[ii][j] += a4[ii] * b4[j];
                    }
                }
                const float* Lr = Xc + rt * 64 * TT;
                const float* S2 = (sec_s >= 0) ? (g_slab + sec_s * CSZ + base) : nullptr;
                float* Vo = g_slab + f * CSZ + base;
                float q1 = 0, q2 = 0, q3 = 0, q4 = 0, q5 = 0, q6 = 0;
                #pragma unroll
                for (int ii = 0; ii < 4; ii++) {
                    int n = ty + 16 * ii;
                    float4 lv = ldcg4(Lr + n * TT + (tx << 2));
                    float4 sv = S2 ? ldcg4(S2 + n * TT + (tx << 2))
                                   : make_float4(0.f, 0.f, 0.f, 0.f);
                    float4 vv = make_float4(acc[ii][0], acc[ii][1], acc[ii][2], acc[ii][3]);
                    stcg4(Vo + n * TT + (tx << 2), vv);
                    q1 += vv.x * lv.x + vv.y * lv.y + vv.z * lv.z + vv.w * lv.w;
                    q2 += vv.x * sv.x + vv.y * sv.y + vv.z * sv.z + vv.w * sv.w;
                    q3 += vv.x * vv.x + vv.y * vv.y + vv.z * vv.z + vv.w * vv.w;
                    q4 += lv.x * sv.x + lv.y * sv.y + lv.z * sv.z + lv.w * sv.w;
                    q5 += lv.x * lv.x + lv.y * lv.y + lv.z * lv.z + lv.w * lv.w;
                    q6 += sv.x * sv.x + sv.y * sv.y + sv.z * sv.z + sv.w * sv.w;
                }
                float r6[6] = {q1, q2, q3, q4, q5, q6};
                #pragma unroll
                for (int s = 0; s < 6; s++) {
                    float w = warp_sum(r6[s]);
                    if ((tid & 31) == 0) red[tid >> 5][s] = w;
                }
                __syncthreads();
                if (tid < 6) {
                    float t = 0.f;
                    #pragma unroll
                    for (int w = 0; w < 8; w++) t += red[w][tid];
                    __stcg(&g_part[pp][chain][rt][tid], t);
                }
                __syncthreads();
            }
            pV = f; pL = last_s; pS = sec_s; pR = r; pPP = pp;
            pp ^= 1; sec_s = last_s; last_s = f; last_t = f; sec_t = -1; r++;
            grid_sync();
        }
        for (int j = 0; j < 5; j++) {
            int f = -1;
            #pragma unroll
            for (int k = 5; k >= 0; k--)
                if (k != last_s && k != sec_s && k != last_t && k != sec_t) f = k;
            // ---------------- TEMPORAL PHASE (step r) ----------------
            // reload Lt into s0 (spatial phases clobber it)
            #pragma unroll
            for (int it = 0; it < 4; it++) {
                int li = it * 256 + tid;
                int rr = li >> 4, c4 = (li & 15) << 2;
                *(float4*)&s0[rr][c4] = *(const float4*)(Lt + rr * TT + c4);
            }
            #pragma unroll 1
            for (int tt = bid; tt < 512; tt += NB) {
                int chain = tt >> 3, rt = tt & 7;
                int base = chain * SLAB + rt * 64 * TT;
                if (pV >= 0) {              // pV == last_t: prologue feeds GEMM
                    if (tid == 0) derive_scalars(pPP, chain, pR, scal);
                    __syncthreads();        // scal + s0 ready, s1 free
                    update_tile(base, pV, pL, pS, scal, s1, true, tid);
                } else {
                    __syncthreads();        // s0 ready, s1 free
                    const float* X = g_slab + last_t * CSZ + base;
                    #pragma unroll
                    for (int it = 0; it < 4; it++) {
                        int idx = it * 256 + tid;
                        int n = idx >> 4, t4 = (idx & 15) << 2;
                        *(float4*)&s1[n][t4] = ldcg4(X + n * TT + t4);
                    }
                }
                __syncthreads();            // s1 ready
                float acc[4][4] = {};
                #pragma unroll 8
                for (int k = 0; k < 64; k++) {
                    float b4[4];
                    *(float4*)b4 = *(float4*)&s0[k][tx << 2];   // Lt[k][u]
                    float a4[4];
                    #pragma unroll
                    for (int ii = 0; ii < 4; ii++) a4[ii] = s1[ty + 16 * ii][k];
                    #pragma unroll
                    for (int ii = 0; ii < 4; ii++)
                        #pragma unroll
                        for (int j = 0; j < 4; j++) acc[ii][j] += a4[ii] * b4[j];
                }
                const float* S2 = (sec_t >= 0) ? (g_slab + sec_t * CSZ + base) : nullptr;
                float* Vo = g_slab + f * CSZ + base;
                float q1 = 0, q2 = 0, q3 = 0, q4 = 0, q5 = 0, q6 = 0;
                #pragma unroll
                for (int ii = 0; ii < 4; ii++) {
                    int n = ty + 16 * ii;
                    float4 lv = *(float4*)&s1[n][tx << 2];      // m_last at (n,u)
                    float4 sv = S2 ? ldcg4(S2 + n * TT + (tx << 2))
                                   : make_float4(0.f, 0.f, 0.f, 0.f);
                    float4 vv = make_float4(acc[ii][0], acc[ii][1], acc[ii][2], acc[ii][3]);
                    stcg4(Vo + n * TT + (tx << 2), vv);
                    q1 += vv.x * lv.x + vv.y * lv.y + vv.z * lv.z + vv.w * lv.w;
                    q2 += vv.x * sv.x + vv.y * sv.y + vv.z * sv.z + vv.w * sv.w;
                    q3 += vv.x * vv.x + vv.y * vv.y + vv.z * vv.z + vv.w * vv.w;
                    q4 += lv.x * sv.x + lv.y * sv.y + lv.z * sv.z + lv.w * sv.w;
                    q5 += lv.x * lv.x + lv.y * lv.y + lv.z * lv.z + lv.w * lv.w;
                    q6 += sv.x * sv.x + sv.y * sv.y + sv.z * sv.z + sv.w * sv.w;
                }
                float r6[6] = {q1, q2, q3, q4, q5, q6};
                #pragma unroll
                for (int s = 0; s < 6; s++) {
                    float w = warp_sum(r6[s]);
                    if ((tid & 31) == 0) red[tid >> 5][s] = w;
                }
                __syncthreads();
                if (tid < 6) {
                    float t = 0.f;
                    #pragma unroll
                    for (int w = 0; w < 8; w++) t += red[w][tid];
                    __stcg(&g_part[pp][chain][rt][tid], t);
                }
                __syncthreads();
            }
            pV = f; pL = last_t; pS = sec_t; pR = r; pPP = pp;
            pp ^= 1; sec_t = last_t; last_t = f; r++;
            grid_sync();
        }
    }
    // ---------------- final pending update (r = 65): A += theta*m ----------
    #pragma unroll 1
    for (int tt = bid; tt < 512; tt += NB) {
        int chain = tt >> 3, rt = tt & 7;
        int base = chain * SLAB + rt * 64 * TT;
        if (tid == 0) derive_scalars(pPP, chain, pR, scal);
        __syncthreads();
        float d1 = scal[0], d2 = scal[1], inv = scal[2], th = scal[3];
        const float* V  = g_slab + pV * CSZ + base;
        const float* Lp = g_slab + pL * CSZ + base;
        const float* Sp = (pS >= 0) ? (g_slab + pS * CSZ + base) : nullptr;
        float* A = g_slab + ACCS * CSZ + base;
        #pragma unroll
        for (int it = 0; it < 4; it++) {
            int o = (it * 256 + tid) * 4;
            float4 v = ldcg4(V + o);
            float4 l = ldcg4(Lp + o);
            float4 s4 = Sp ? ldcg4(Sp + o) : make_float4(0.f, 0.f, 0.f, 0.f);
            float4 a = *(float4*)(A + o);
            a.x += th * (v.x - d1 * l.x - d2 * s4.x) * inv;
            a.y += th * (v.y - d1 * l.y - d2 * s4.y) * inv;
            a.z += th * (v.z - d1 * l.z - d2 * s4.z) * inv;
            a.w += th * (v.w - d1 * l.w - d2 * s4.w) * inv;
            *(float4*)(A + o) = a;
        }
        __syncthreads();
    }
}

// ---------------------------------------------------------------------------
// final: out[b,o,n,t] = BN(W_mlp @ cat(x, x_st) + b)   with BN folded into W,b
// ---------------------------------------------------------------------------
__global__ void __launch_bounds__(256) k_final(const float* __restrict__ x,
                                               const float* __restrict__ wm,
                                               const float* __restrict__ bm,
                                               const float* __restrict__ gam,
                                               const float* __restrict__ bet,
                                               const float* __restrict__ mea,
                                               const float* __restrict__ var,
                                               float* __restrict__ out) {
    int b = blockIdx.x;
    int ng = blockIdx.y;                 // group of 4 n values
    __shared__ float sV[4][32][65];
    __shared__ float sW[64][32];
    __shared__ float sb2[64];
    int tid = threadIdx.x;

    for (int i = tid; i < 2048; i += 256) {
        int o = i >> 5, c = i & 31;
        float inv = gam[o] * rsqrtf(var[o] + 1e-5f);
        sW[o][c] = wm[o * 32 + c] * inv;
    }
    if (tid < 64) {
        float inv = gam[tid] * rsqrtf(var[tid] + 1e-5f);
        sb2[tid] = bm[tid] * inv + bet[tid] - mea[tid] * inv;
    }
    for (int i = tid; i < 8192; i += 256) {
        int t = i & 63, c = (i >> 6) & 31, nn = i >> 11;
        int n = ng * 4 + nn;
        float val;
        if (c < 16) val = x[((b * CC + c) * NN + n) * TT + t];
        else        val = g_slab[ACCS * CSZ + (b * CC + (c - 16)) * SLAB + n * TT + t];
        sV[nn][c][t] = val;
    }
    __syncthreads();

    int tg = tid & 63, og = tid >> 6;
    for (int oo = 0; oo < 16; oo++) {
        int o = og * 16 + oo;
        float w[32];
        #pragma unroll
        for (int c = 0; c < 32; c++) w[c] = sW[o][c];
        float bb = sb2[o];
        #pragma unroll
        for (int nn = 0; nn < 4; nn++) {
            float s = bb;
            #pragma unroll
            for (int c = 0; c < 32; c++) s += w[c] * sV[nn][c][tg];
            int n = ng * 4 + nn;
            out[((b * 64 + o) * NN + n) * TT + tg] = s;
        }
    }
}

// ---------------------------------------------------------------------------
// host: 4-node launch sequence (graph-capturable: launches only)
// ---------------------------------------------------------------------------
extern "C" void kernel_launch(void* const* d_in, const int* in_sizes, int n_in,
                              void* d_out, int out_size) {
    const float* x   = (const float*)d_in[0];
    const float* Ls  = (const float*)d_in[1];
    const float* Lt  = (const float*)d_in[2];
    const float* STE = (const float*)d_in[3];
    const float* w1  = (const float*)d_in[4];
    const float* b1  = (const float*)d_in[5];
    const float* w2  = (const float*)d_in[6];
    const float* b2  = (const float*)d_in[7];
    const float* wm  = (const float*)d_in[8];
    const float* bm  = (const float*)d_in[9];
    const float* gam = (const float*)d_in[10];
    const float* bet = (const float*)d_in[11];
    const float* mea = (const float*)d_in[12];
    const float* var = (const float*)d_in[13];
    float* out = (float*)d_out;
    (void)in_sizes; (void)n_in; (void)out_size;

    k_theta<<<1, 288>>>(STE, w1, b1, w2, b2);
    k_init<<<64, 256>>>(x);
    k_persist<<<NB, 256>>>(Ls, Lt);
    k_final<<<dim3(4, 128), 256>>>(x, wm, bm, gam, bet, mea, var, out);
}

// round 9
// speedup vs baseline: 1.5052x; 1.0272x over previous
#include <cuda_runtime.h>

// ---------------------------------------------------------------------------
// ST_Block: 66-step spatio-temporal orthogonal basis recursion + fused MLP/BN.
//
// R9: the 64 chains are fully independent, so the R8 grid-wide barrier is
// replaced by PER-CHAIN arrival counters: each of a chain's 8 tile CTAs
// atomically arrives after publishing its 6 dot partials for step r; a
// consumer of step r scalars spins until g_arrive[chain] >= 8*r. Chains
// free-run; no global straggler coupling. g_part is 4-deep (step mod 4) to
// tolerate the <=2-step intra-chain drift. All 256 blocks are co-resident
// (35 KB smem, <=128 regs -> 2 CTAs/SM) so the spin cannot deadlock.
// Mutable slab traffic stays on __ldcg/__stcg (L2-coherent); accumulator is
// tile-owner-private (L1 OK); Ls/Lt immutable (L1).
// ---------------------------------------------------------------------------

#define BB   4
#define CC   16
#define CH   64              // B*C chains
#define NN   512
#define TT   64
#define SLAB (NN*TT)         // 32768 floats per chain slab
#define CSZ  (CH*SLAB)       // floats per full slab
#define NSLAB 7
#define ACCS  6              // slab index reserved for x_st accumulator
#define RTOT  66
#define NB    256            // persistent grid size (co-residency guaranteed)

__device__ __align__(16) float g_slab[NSLAB * CSZ];   // ~58.7 MB scratch
__device__ float g_part[4][CH][8][6];                 // step-mod-4 dot partials
__device__ float g_theta[BB][RTOT];
__device__ int   g_arrive[CH];                        // per-chain arrival counters

__device__ __forceinline__ float4 ldcg4(const float* p) {
    return __ldcg((const float4*)p);
}
__device__ __forceinline__ void stcg4(float* p, float4 v) {
    __stcg((float4*)p, v);
}

__device__ __forceinline__ float warp_sum(float v) {
    v += __shfl_down_sync(0xffffffffu, v, 16);
    v += __shfl_down_sync(0xffffffffu, v, 8);
    v += __shfl_down_sync(0xffffffffu, v, 4);
    v += __shfl_down_sync(0xffffffffu, v, 2);
    v += __shfl_down_sync(0xffffffffu, v, 1);
    return v;
}

// Derive d1, d2, 1/norm, theta from the 6 summed dots (L2-coherent reads).
//   d1 = <V,L>;  d2 = <V,S> - d1*<L,S>
//   ||rst2||^2 = p3 - 2 d1 p1 - 2 d2 p2 + d1^2 p5 + d2^2 p6 + 2 d1 d2 p4
__device__ __forceinline__ void derive_scalars(int buf, int chain, int rUpd,
                                               float* sc) {
    float p0 = 0, p1 = 0, p2 = 0, p3 = 0, p4 = 0, p5 = 0;
    #pragma unroll
    for (int tl = 0; tl < 8; tl++) {
        const float* q = &g_part[buf][chain][tl][0];
        p0 += __ldcg(q + 0); p1 += __ldcg(q + 1); p2 += __ldcg(q + 2);
        p3 += __ldcg(q + 3); p4 += __ldcg(q + 4); p5 += __ldcg(q + 5);
    }
    float d1 = p0;
    float d2 = p1 - d1 * p3;
    float n2 = p2 - 2.f * d1 * p0 - 2.f * d2 * p1
             + d1 * d1 * p4 + d2 * d2 * p5 + 2.f * d1 * d2 * p3;
    sc[0] = d1;
    sc[1] = d2;
    sc[2] = 1.f / fmaxf(sqrtf(fmaxf(n2, 0.f)), 1e-8f);
    sc[3] = g_theta[chain >> 4][rUpd];
}

// Spin until all 8 tiles of `chain` have published step `step` partials,
// then acquire. Called by one thread; caller broadcasts via smem+bar.
__device__ __forceinline__ void wait_chain(int chain, int step) {
    int target = 8 * step;
    while (*(volatile int*)&g_arrive[chain] < target) __nanosleep(32);
    __threadfence();
}

// Tile-local pending update: V <- m = (V - d1 L - d2 S)/norm ; A += theta*m.
// Optionally also deposits m into smem (temporal phases feed the GEMM).
__device__ __forceinline__ void update_tile(int base, int pV, int pL, int pS,
                                            const float* sc, float (*s1)[68],
                                            bool toSmem, int tid) {
    float d1 = sc[0], d2 = sc[1], inv = sc[2], th = sc[3];
    float*       V  = g_slab + pV * CSZ + base;
    const float* Lp = g_slab + pL * CSZ + base;
    const float* Sp = (pS >= 0) ? (g_slab + pS * CSZ + base) : nullptr;
    float*       A  = g_slab + ACCS * CSZ + base;
    #pragma unroll
    for (int it = 0; it < 4; it++) {
        int idx = it * 256 + tid;            // 0..1023 float4s over the tile
        int o = idx * 4;
        float4 v = ldcg4(V + o);
        float4 l = ldcg4(Lp + o);
        float4 s4 = Sp ? ldcg4(Sp + o) : make_float4(0.f, 0.f, 0.f, 0.f);
        float4 m;
        m.x = (v.x - d1 * l.x - d2 * s4.x) * inv;
        m.y = (v.y - d1 * l.y - d2 * s4.y) * inv;
        m.z = (v.z - d1 * l.z - d2 * s4.z) * inv;
        m.w = (v.w - d1 * l.w - d2 * s4.w) * inv;
        stcg4(V + o, m);
        float4 a = *(float4*)(A + o);        // A is tile-owner-private: L1 OK
        a.x += th * m.x; a.y += th * m.y; a.z += th * m.z; a.w += th * m.w;
        *(float4*)(A + o) = a;
        if (toSmem) {
            int n = idx >> 4, t4 = (idx & 15) << 2;
            *(float4*)&s1[n][t4] = m;
        }
    }
}

// ---------------------------------------------------------------------------
// theta: tiny MLP on STE; also resets the per-chain arrival counters
// (device globals persist across graph replays).
// ---------------------------------------------------------------------------
__global__ void k_theta(const float* __restrict__ STE, const float* __restrict__ w1,
                        const float* __restrict__ b1, const float* __restrict__ w2,
                        const float* __restrict__ b2) {
    int idx = threadIdx.x;
    if (idx < CH) g_arrive[idx] = 0;
    if (idx >= BB * RTOT) return;
    int b = idx / RTOT, rr = idx % RTOT;
    int q = rr / 11, p = rr % 11;
    float acc = b2[p];
    #pragma unroll
    for (int s = 0; s < 10; s++) {
        float h1 = b1[q];
        #pragma unroll
        for (int t = 0; t < 5; t++)
            h1 += w1[q * 5 + t] * STE[b * 50 + t * 10 + s];
        acc += w2[p * 10 + s] * h1;
    }
    g_theta[b][rr] = fmaxf(acc, 0.f);
}

// ---------------------------------------------------------------------------
// init: m00 = x / max(||x||_F, eps) into slab 0; acc = theta_0 * m00
// ---------------------------------------------------------------------------
__global__ void __launch_bounds__(256) k_init(const float* __restrict__ x) {
    int chain = blockIdx.x;
    const float* xp = x + chain * SLAB;
    float* m = g_slab + 0 * CSZ + chain * SLAB;
    float* a = g_slab + ACCS * CSZ + chain * SLAB;
    int tid = threadIdx.x;

    float s = 0.f;
    #pragma unroll
    for (int i = 0; i < 32; i++) {
        float4 v = *(const float4*)(xp + (i * 256 + tid) * 4);
        s += v.x * v.x + v.y * v.y + v.z * v.z + v.w * v.w;
    }
    __shared__ float red[8];
    __shared__ float sinv;
    float w = warp_sum(s);
    if ((tid & 31) == 0) red[tid >> 5] = w;
    __syncthreads();
    if (tid == 0) {
        float t = 0.f;
        #pragma unroll
        for (int k = 0; k < 8; k++) t += red[k];
        sinv = 1.f / fmaxf(sqrtf(t), 1e-8f);
    }
    __syncthreads();
    float inv = sinv;
    float th = g_theta[chain >> 4][0];
    #pragma unroll
    for (int i = 0; i < 32; i++) {
        int o = (i * 256 + tid) * 4;
        float4 v = *(const float4*)(xp + o);
        float4 mm, aa;
        mm.x = v.x * inv; mm.y = v.y * inv; mm.z = v.z * inv; mm.w = v.w * inv;
        aa.x = th * mm.x; aa.y = th * mm.y; aa.z = th * mm.z; aa.w = th * mm.w;
        *(float4*)(m + o) = mm;
        *(float4*)(a + o) = aa;
    }
}

// ---------------------------------------------------------------------------
// persistent kernel: all 65 steps + final pending update, per-chain sync.
// Tile tt = (chain = tt>>3, rowTile = tt&7); block b owns tiles {b, b+256}.
// ---------------------------------------------------------------------------
__global__ void __launch_bounds__(256, 2) k_persist(
    const float* __restrict__ Ls, const float* __restrict__ Lt)
{
    __shared__ float s0[64][68];
    __shared__ float s1[64][68];
    __shared__ float scal[4];
    __shared__ float red[8][6];
    const int tid = threadIdx.x, bid = blockIdx.x;
    const int tx = tid & 15, ty = tid >> 4;

    int last_s = 0, sec_s = -1, last_t = 0, sec_t = -1;
    int pV = -1, pL = -1, pS = -1, pR = 0;
    int r = 1;

    for (int i = 0; i <= 10; i++) {
        if (i > 0) {
            int f = -1;
            #pragma unroll
            for (int k = 5; k >= 0; k--)
                if (k != last_s && k != sec_s && k != last_t && k != sec_t) f = k;
            // ---------------- SPATIAL PHASE (step r) ----------------
            #pragma unroll 1
            for (int tt = bid; tt < 512; tt += NB) {
                int chain = tt >> 3, rt = tt & 7;
                int base = chain * SLAB + rt * 64 * TT;
                if (pV >= 0) {
                    if (tid == 0) {
                        wait_chain(chain, pR);
                        derive_scalars(pR & 3, chain, pR, scal);
                    }
                    __syncthreads();
                    update_tile(base, pV, pL, pS, scal, s1, false, tid);
                }
                const float* Xc = g_slab + last_s * CSZ + chain * SLAB;
                float acc[4][4] = {};
                for (int kc = 0; kc < 8; kc++) {
                    __syncthreads();
                    #pragma unroll
                    for (int it = 0; it < 4; it++) {
                        int li = it * 256 + tid;
                        int rr = li >> 4, c4 = (li & 15) << 2;
                        *(float4*)&s0[rr][c4] =
                            *(const float4*)(Ls + (rt * 64 + rr) * NN + kc * 64 + c4);
                        *(float4*)&s1[rr][c4] = ldcg4(Xc + (kc * 64 + rr) * TT + c4);
                    }
                    __syncthreads();
                    #pragma unroll 8
                    for (int k = 0; k < 64; k++) {
                        float b4[4];
                        *(float4*)b4 = *(float4*)&s1[k][tx << 2];
                        float a4[4];
                        #pragma unroll
                        for (int ii = 0; ii < 4; ii++) a4[ii] = s0[ty + 16 * ii][k];
                        #pragma unroll
                        for (int ii = 0; ii < 4; ii++)
                            #pragma unroll
                            for (int j = 0; j < 4; j++) acc[ii][j] += a4[ii] * b4[j];
                    }
                }
                const float* Lr = Xc + rt * 64 * TT;
                const float* S2 = (sec_s >= 0) ? (g_slab + sec_s * CSZ + base) : nullptr;
                float* Vo = g_slab + f * CSZ + base;
                float q1 = 0, q2 = 0, q3 = 0, q4 = 0, q5 = 0, q6 = 0;
                #pragma unroll
                for (int ii = 0; ii < 4; ii++) {
                    int n = ty + 16 * ii;
                    float4 lv = ldcg4(Lr + n * TT + (tx << 2));
                    float4 sv = S2 ? ldcg4(S2 + n * TT + (tx << 2))
                                   : make_float4(0.f, 0.f, 0.f, 0.f);
                    float4 vv = make_float4(acc[ii][0], acc[ii][1], acc[ii][2], acc[ii][3]);
                    stcg4(Vo + n * TT + (tx << 2), vv);
                    q1 += vv.x * lv.x + vv.y * lv.y + vv.z * lv.z + vv.w * lv.w;
                    q2 += vv.x * sv.x + vv.y * sv.y + vv.z * sv.z + vv.w * sv.w;
                    q3 += vv.x * vv.x + vv.y * vv.y + vv.z * vv.z + vv.w * vv.w;
                    q4 += lv.x * sv.x + lv.y * sv.y + lv.z * sv.z + lv.w * sv.w;
                    q5 += lv.x * lv.x + lv.y * lv.y + lv.z * lv.z + lv.w * lv.w;
                    q6 += sv.x * sv.x + sv.y * sv.y + sv.z * sv.z + sv.w * sv.w;
                }
                float r6[6] = {q1, q2, q3, q4, q5, q6};
                #pragma unroll
                for (int s = 0; s < 6; s++) {
                    float w = warp_sum(r6[s]);
                    if ((tid & 31) == 0) red[tid >> 5][s] = w;
                }
                __threadfence();            // publish this tile's slab stores
                __syncthreads();
                if (tid == 0) {             // publish partials, then arrive
                    #pragma unroll
                    for (int s = 0; s < 6; s++) {
                        float t = 0.f;
                        #pragma unroll
                        for (int w = 0; w < 8; w++) t += red[w][s];
                        __stcg(&g_part[r & 3][chain][rt][s], t);
                    }
                    __threadfence();
                    atomicAdd(&g_arrive[chain], 1);
                }
                __syncthreads();
            }
            pV = f; pL = last_s; pS = sec_s; pR = r;
            sec_s = last_s; last_s = f; last_t = f; sec_t = -1; r++;
        }
        for (int j = 0; j < 5; j++) {
            int f = -1;
            #pragma unroll
            for (int k = 5; k >= 0; k--)
                if (k != last_s && k != sec_s && k != last_t && k != sec_t) f = k;
            // ---------------- TEMPORAL PHASE (step r) ----------------
            // reload Lt into s0 (spatial phases clobber it)
            #pragma unroll
            for (int it = 0; it < 4; it++) {
                int li = it * 256 + tid;
                int rr = li >> 4, c4 = (li & 15) << 2;
                *(float4*)&s0[rr][c4] = *(const float4*)(Lt + rr * TT + c4);
            }
            #pragma unroll 1
            for (int tt = bid; tt < 512; tt += NB) {
                int chain = tt >> 3, rt = tt & 7;
                int base = chain * SLAB + rt * 64 * TT;
                if (pV >= 0) {              // pV == last_t: prologue feeds GEMM
                    if (tid == 0) {
                        wait_chain(chain, pR);
                        derive_scalars(pR & 3, chain, pR, scal);
                    }
                    __syncthreads();        // scal + s0 ready, s1 free
                    update_tile(base, pV, pL, pS, scal, s1, true, tid);
                } else {
                    __syncthreads();        // s0 ready, s1 free
                    const float* X = g_slab + last_t * CSZ + base;
                    #pragma unroll
                    for (int it = 0; it < 4; it++) {
                        int idx = it * 256 + tid;
                        int n = idx >> 4, t4 = (idx & 15) << 2;
                        *(float4*)&s1[n][t4] = ldcg4(X + n * TT + t4);
                    }
                }
                __syncthreads();            // s1 ready
                float acc[4][4] = {};
                #pragma unroll 8
                for (int k = 0; k < 64; k++) {
                    float b4[4];
                    *(float4*)b4 = *(float4*)&s0[k][tx << 2];   // Lt[k][u]
                    float a4[4];
                    #pragma unroll
                    for (int ii = 0; ii < 4; ii++) a4[ii] = s1[ty + 16 * ii][k];
                    #pragma unroll
                    for (int ii = 0; ii < 4; ii++)
                        #pragma unroll
                        for (int j = 0; j < 4; j++) acc[ii][j] += a4[ii] * b4[j];
                }
                const float* S2 = (sec_t >= 0) ? (g_slab + sec_t * CSZ + base) : nullptr;
                float* Vo = g_slab + f * CSZ + base;
                float q1 = 0, q2 = 0, q3 = 0, q4 = 0, q5 = 0, q6 = 0;
                #pragma unroll
                for (int ii = 0; ii < 4; ii++) {
                    int n = ty + 16 * ii;
                    float4 lv = *(float4*)&s1[n][tx << 2];      // m_last at (n,u)
                    float4 sv = S2 ? ldcg4(S2 + n * TT + (tx << 2))
                                   : make_float4(0.f, 0.f, 0.f, 0.f);
                    float4 vv = make_float4(acc[ii][0], acc[ii][1], acc[ii][2], acc[ii][3]);
                    stcg4(Vo + n * TT + (tx << 2), vv);
                    q1 += vv.x * lv.x + vv.y * lv.y + vv.z * lv.z + vv.w * lv.w;
                    q2 += vv.x * sv.x + vv.y * sv.y + vv.z * sv.z + vv.w * sv.w;
                    q3 += vv.x * vv.x + vv.y * vv.y + vv.z * vv.z + vv.w * vv.w;
                    q4 += lv.x * sv.x + lv.y * sv.y + lv.z * sv.z + lv.w * sv.w;
                    q5 += lv.x * lv.x + lv.y * lv.y + lv.z * lv.z + lv.w * lv.w;
                    q6 += sv.x * sv.x + sv.y * sv.y + sv.z * sv.z + sv.w * sv.w;
                }
                float r6[6] = {q1, q2, q3, q4, q5, q6};
                #pragma unroll
                for (int s = 0; s < 6; s++) {
                    float w = warp_sum(r6[s]);
                    if ((tid & 31) == 0) red[tid >> 5][s] = w;
                }
                __threadfence();            // publish this tile's slab stores
                __syncthreads();
                if (tid == 0) {
                    #pragma unroll
                    for (int s = 0; s < 6; s++) {
                        float t = 0.f;
                        #pragma unroll
                        for (int w = 0; w < 8; w++) t += red[w][s];
                        __stcg(&g_part[r & 3][chain][rt][s], t);
                    }
                    __threadfence();
                    atomicAdd(&g_arrive[chain], 1);
                }
                __syncthreads();
            }
            pV = f; pL = last_t; pS = sec_t; pR = r;
            sec_t = last_t; last_t = f; r++;
        }
    }
    // ---------------- final pending update (r = 65): A += theta*m ----------
    #pragma unroll 1
    for (int tt = bid; tt < 512; tt += NB) {
        int chain = tt >> 3, rt = tt & 7;
        int base = chain * SLAB + rt * 64 * TT;
        if (tid == 0) {
            wait_chain(chain, pR);
            derive_scalars(pR & 3, chain, pR, scal);
        }
        __syncthreads();
        float d1 = scal[0], d2 = scal[1], inv = scal[2], th = scal[3];
        const float* V  = g_slab + pV * CSZ + base;
        const float* Lp = g_slab + pL * CSZ + base;
        const float* Sp = (pS >= 0) ? (g_slab + pS * CSZ + base) : nullptr;
        float* A = g_slab + ACCS * CSZ + base;
        #pragma unroll
        for (int it = 0; it < 4; it++) {
            int o = (it * 256 + tid) * 4;
            float4 v = ldcg4(V + o);
            float4 l = ldcg4(Lp + o);
            float4 s4 = Sp ? ldcg4(Sp + o) : make_float4(0.f, 0.f, 0.f, 0.f);
            float4 a = *(float4*)(A + o);
            a.x += th * (v.x - d1 * l.x - d2 * s4.x) * inv;
            a.y += th * (v.y - d1 * l.y - d2 * s4.y) * inv;
            a.z += th * (v.z - d1 * l.z - d2 * s4.z) * inv;
            a.w += th * (v.w - d1 * l.w - d2 * s4.w) * inv;
            *(float4*)(A + o) = a;
        }
        __syncthreads();
    }
}

// ---------------------------------------------------------------------------
// final: out[b,o,n,t] = BN(W_mlp @ cat(x, x_st) + b)   with BN folded into W,b
// R9: weights read straight from smem in the inner product (no w[32] register
// image) -> ~30 regs, high occupancy.
// ---------------------------------------------------------------------------
__global__ void __launch_bounds__(256) k_final(const float* __restrict__ x,
                                               const float* __restrict__ wm,
                                               const float* __restrict__ bm,
                                               const float* __restrict__ gam,
                                               const float* __restrict__ bet,
                                               const float* __restrict__ mea,
                                               const float* __restrict__ var,
                                               float* __restrict__ out) {
    int b = blockIdx.x;
    int ng = blockIdx.y;                 // group of 4 n values
    __shared__ float sV[4][32][65];
    __shared__ float sW[64][32];
    __shared__ float sb2[64];
    int tid = threadIdx.x;

    for (int i = tid; i < 2048; i += 256) {
        int o = i >> 5, c = i & 31;
        float inv = gam[o] * rsqrtf(var[o] + 1e-5f);
        sW[o][c] = wm[o * 32 + c] * inv;
    }
    if (tid < 64) {
        float inv = gam[tid] * rsqrtf(var[tid] + 1e-5f);
        sb2[tid] = bm[tid] * inv + bet[tid] - mea[tid] * inv;
    }
    for (int i = tid; i < 8192; i += 256) {
        int t = i & 63, c = (i >> 6) & 31, nn = i >> 11;
        int n = ng * 4 + nn;
        float val;
        if (c < 16) val = x[((b * CC + c) * NN + n) * TT + t];
        else        val = g_slab[ACCS * CSZ + (b * CC + (c - 16)) * SLAB + n * TT + t];
        sV[nn][c][t] = val;
    }
    __syncthreads();

    int tg = tid & 63, og = tid >> 6;
    #pragma unroll 1
    for (int oo = 0; oo < 16; oo++) {
        int o = og * 16 + oo;
        float bb = sb2[o];
        float a0 = bb, a1 = bb, a2 = bb, a3 = bb;
        #pragma unroll
        for (int c = 0; c < 32; c++) {
            float w = sW[o][c];
            a0 += w * sV[0][c][tg];
            a1 += w * sV[1][c][tg];
            a2 += w * sV[2][c][tg];
            a3 += w * sV[3][c][tg];
        }
        int n0 = ng * 4;
        float* op = out + ((b * 64 + o) * NN + n0) * TT + tg;
        op[0 * TT] = a0;
        op[1 * TT] = a1;
        op[2 * TT] = a2;
        op[3 * TT] = a3;
    }
}

// ---------------------------------------------------------------------------
// host: 4-node launch sequence (graph-capturable: launches only)
// ---------------------------------------------------------------------------
extern "C" void kernel_launch(void* const* d_in, const int* in_sizes, int n_in,
                              void* d_out, int out_size) {
    const float* x   = (const float*)d_in[0];
    const float* Ls  = (const float*)d_in[1];
    const float* Lt  = (const float*)d_in[2];
    const float* STE = (const float*)d_in[3];
    const float* w1  = (const float*)d_in[4];
    const float* b1  = (const float*)d_in[5];
    const float* w2  = (const float*)d_in[6];
    const float* b2  = (const float*)d_in[7];
    const float* wm  = (const float*)d_in[8];
    const float* bm  = (const float*)d_in[9];
    const float* gam = (const float*)d_in[10];
    const float* bet = (const float*)d_in[11];
    const float* mea = (const float*)d_in[12];
    const float* var = (const float*)d_in[13];
    float* out = (float*)d_out;
    (void)in_sizes; (void)n_in; (void)out_size;

    k_theta<<<1, 288>>>(STE, w1, b1, w2, b2);
    k_init<<<64, 256>>>(x);
    k_persist<<<NB, 256>>>(Ls, Lt);
    k_final<<<dim3(4, 128), 256>>>(x, wm, bm, gam, bet, mea, var, out);
}